// round 1
// baseline (speedup 1.0000x reference)
#include <cuda_runtime.h>
#include <math.h>

// Problem constants (fixed by setup_inputs / init config)
#define MESH 129
#define MM   (MESH*MESH)        // 16641
#define NB   4
#define NP   512
#define BP   (NB*NP)            // 2048
#define KOFF 64                 // k = idx - 64, k in [-64, 64]

// Scratch (static __device__ globals; no allocation allowed)
__device__ float2 g_A[BP*MESH];   // per-point 1D DFT along axis 0 (x-coordinate)
__device__ float2 g_B[BP*MESH];   // per-point 1D DFT along axis 1 (y-coordinate)
__device__ float2 g_T[NB*MM];     // T[b,k1,k2] = sum_p A[p,k1]*B[p,k2]
__device__ float2 g_W[MM];        // (w_channel0, w_channel1) real weights

// ---------------------------------------------------------------------------
// k0: weight table W_c[k1,k2] = deconv^2 * mult_c * scale / M^2
// deconv = (pi/tau) e^{tau*(kx^2+ky^2)}, mult_c = amp_c*4pi/(k2 + (mu*shift_c)^2)
// scale = 1/(M^2 (2pi)^2 2); extra 1/M^2 from Parseval.
// ---------------------------------------------------------------------------
__global__ void k_weights(const float* __restrict__ s0, const float* __restrict__ s1,
                          const float* __restrict__ a0, const float* __restrict__ a1)
{
    int idx = blockIdx.x * blockDim.x + threadIdx.x;
    if (idx >= MM) return;
    int i = idx / MESH;
    int j = idx - i * MESH;
    float kx = (float)(i - KOFF);
    float ky = (float)(j - KOFF);
    float k2s = kx * kx + ky * ky;

    const double PI_D  = 3.14159265358979323846;
    const double TAU_D = 12.0 / ((double)MESH * (double)MESH);
    double pref = (PI_D / TAU_D) * (PI_D / TAU_D) * 4.0 * PI_D
                / ((double)MESH * MESH * MESH * MESH * (2.0 * PI_D) * (2.0 * PI_D) * 2.0);

    float e = expf(2.0f * (float)TAU_D * k2s);
    float sh0 = s0[0], sh1 = s1[0];
    float w0 = (float)pref * a0[0] * e / (k2s + sh0 * sh0);
    float w1 = (float)pref * a1[0] * e / (k2s + sh1 * sh1);
    g_W[idx] = make_float2(w0, w1);
}

// ---------------------------------------------------------------------------
// k1: closed-form 1D DFTs of the periodic spread Gaussian.
// A[p,k] = M*sqrt(4 pi tau)/L * sum_{j=-1..1} e^{-tau m^2} e^{-i m x},  m = k + j*M
// ---------------------------------------------------------------------------
__global__ void k_ab(const float* __restrict__ x)
{
    int bp = blockIdx.x;
    float x0 = x[bp * 2 + 0];
    float x1 = x[bp * 2 + 1];

    const double PI_D  = 3.14159265358979323846;
    const double TWO_PI = 6.28318530717958647692;
    const double TAU_D = 12.0 / ((double)MESH * (double)MESH);
    const float  tauf  = (float)TAU_D;
    const float  Cst   = (float)((double)MESH * sqrt(4.0 * PI_D * TAU_D) / TWO_PI);

    for (int t = threadIdx.x; t < 2 * MESH; t += blockDim.x) {
        int dim = (t >= MESH) ? 1 : 0;
        int k   = t - dim * MESH;
        float xx = dim ? x1 : x0;
        float kk = (float)(k - KOFF);

        float re = 0.0f, im = 0.0f;
        #pragma unroll
        for (int j = -1; j <= 1; j++) {
            float m = kk + (float)(MESH * j);
            float w = expf(-tauf * m * m);
            // accurate phase: reduce m*x mod 2pi in double (tiny op count)
            double ang = (double)m * (double)xx;
            ang -= TWO_PI * floor(ang / TWO_PI);
            float s, c;
            sincosf((float)ang, &s, &c);
            re += w * c;       // e^{-i m x} = cos - i sin
            im -= w * s;
        }
        float2 v = make_float2(Cst * re, Cst * im);
        if (dim) g_B[bp * MESH + k] = v;
        else     g_A[bp * MESH + k] = v;
    }
}

// ---------------------------------------------------------------------------
// k2: T[b,k1,k2] = sum_p A[bp,k1] * B[bp,k2]   (complex outer-product sum)
// Tiled 16x16 over (k1,k2), p in chunks of 32 via shared memory.
// ---------------------------------------------------------------------------
__global__ void k_T()
{
    __shared__ float2 At[32][16];
    __shared__ float2 Bt[32][16];

    int b  = blockIdx.z;
    int k1 = blockIdx.y * 16 + threadIdx.y;
    int k2 = blockIdx.x * 16 + threadIdx.x;
    int tid = threadIdx.y * 16 + threadIdx.x;

    float2 acc = make_float2(0.0f, 0.0f);

    for (int p0 = 0; p0 < NP; p0 += 32) {
        for (int l = tid; l < 32 * 16; l += 256) {
            int i = l >> 4;
            int j = l & 15;
            int kk1 = blockIdx.y * 16 + j;
            int kk2 = blockIdx.x * 16 + j;
            int row = (b * NP + p0 + i) * MESH;
            At[i][j] = (kk1 < MESH) ? g_A[row + kk1] : make_float2(0.0f, 0.0f);
            Bt[i][j] = (kk2 < MESH) ? g_B[row + kk2] : make_float2(0.0f, 0.0f);
        }
        __syncthreads();
        #pragma unroll 8
        for (int i = 0; i < 32; i++) {
            float2 a  = At[i][threadIdx.y];
            float2 bb = Bt[i][threadIdx.x];
            acc.x += a.x * bb.x - a.y * bb.y;
            acc.y += a.x * bb.y + a.y * bb.x;
        }
        __syncthreads();
    }
    if (k1 < MESH && k2 < MESH)
        g_T[b * MM + k1 * MESH + k2] = acc;
}

// ---------------------------------------------------------------------------
// k3: E_c[b,p] = sum_k W_c[k] * Re[ conj(S_p[k]) * (T[b,k] - S_p[k]) ]
//     with S_p[k1,k2] = A[p,k1]*B[p,k2] generated on the fly.
// One block = 8 points of one batch; T and W streamed once per block (L2-hot).
// ---------------------------------------------------------------------------
#define PTS 8
__global__ void k_energy(float* __restrict__ out)
{
    __shared__ float2 As[PTS * MESH];
    __shared__ float2 Bs[PTS * MESH];
    __shared__ float  red[16][8];

    int b  = blockIdx.y;
    int p0 = blockIdx.x * PTS;
    int tid = threadIdx.x;      // 256 threads

    for (int l = tid; l < PTS * MESH; l += 256) {
        int p = l / MESH;
        int k = l - p * MESH;
        int row = (b * NP + p0 + p) * MESH;
        As[l] = g_A[row + k];
        Bs[l] = g_B[row + k];
    }
    __syncthreads();

    float e[PTS][2];
    #pragma unroll
    for (int p = 0; p < PTS; p++) { e[p][0] = 0.0f; e[p][1] = 0.0f; }

    const float2* __restrict__ Tb = g_T + b * MM;

    for (int idx = tid; idx < MM; idx += 256) {
        int k1 = idx / MESH;
        int k2 = idx - k1 * MESH;
        float2 t = Tb[idx];
        float2 w = g_W[idx];
        #pragma unroll
        for (int p = 0; p < PTS; p++) {
            float2 a  = As[p * MESH + k1];
            float2 bb = Bs[p * MESH + k2];
            float sx = a.x * bb.x - a.y * bb.y;
            float sy = a.x * bb.y + a.y * bb.x;
            // Re(conj(S)*T) - |S|^2
            float v = sx * t.x + sy * t.y - sx * sx - sy * sy;
            e[p][0] += w.x * v;
            e[p][1] += w.y * v;
        }
    }

    // reduce 16 accumulators across 256 threads
    int lane = tid & 31, warp = tid >> 5;
    #pragma unroll
    for (int v = 0; v < 16; v++) {
        float val = e[v >> 1][v & 1];
        #pragma unroll
        for (int off = 16; off; off >>= 1)
            val += __shfl_down_sync(0xffffffffu, val, off);
        if (lane == 0) red[v][warp] = val;
    }
    __syncthreads();
    if (tid < 16) {
        float s = 0.0f;
        #pragma unroll
        for (int wq = 0; wq < 8; wq++) s += red[tid][wq];
        int p = tid >> 1, c = tid & 1;
        out[(b * NP + p0 + p) * 2 + c] = s;
    }
}

// ---------------------------------------------------------------------------
extern "C" void kernel_launch(void* const* d_in, const int* in_sizes, int n_in,
                              void* d_out, int out_size)
{
    const float* x  = (const float*)d_in[0];
    const float* s0 = (const float*)d_in[1];
    const float* s1 = (const float*)d_in[2];
    const float* a0 = (const float*)d_in[3];
    const float* a1 = (const float*)d_in[4];

    k_weights<<<(MM + 255) / 256, 256>>>(s0, s1, a0, a1);
    k_ab<<<BP, 256>>>(x);
    dim3 gT((MESH + 15) / 16, (MESH + 15) / 16, NB);
    dim3 bT(16, 16);
    k_T<<<gT, bT>>>();
    dim3 gE(NP / PTS, NB);
    k_energy<<<gE, 256>>>((float*)d_out);
}

// round 2
// speedup vs baseline: 2.1479x; 2.1479x over previous
#include <cuda_runtime.h>
#include <math.h>

#define MESH  129
#define MM    (MESH*MESH)        // 16641
#define NB    4
#define NP    512
#define BP    (NB*NP)            // 2048
#define KOFF  64
#define HALF  8321               // linear modes idx<=center(64,64); rest by Hermitian symmetry
#define TROWS 65                 // k1 rows needed (0..64)
#define TN    (TROWS*MESH)       // 8385
#define PC    4                  // p-chunks in k_T
#define NC    4                  // mode chunks in k_energy
#define PTS   8                  // points per k_energy block

// Scratch (__device__ globals; no allocation allowed)
__device__ float2 g_A[BP*MESH];
__device__ float2 g_B[BP*MESH];
__device__ float2 g_Tp[PC*NB*TN];   // partial T per p-chunk
__device__ float4 g_TW[NB*TN];      // fused (T.re, T.im, w0, w1)
__device__ float2 g_W[HALF];
__device__ float  g_P[NC*BP*2];     // deterministic partial energies

// ---------------------------------------------------------------------------
// k0: weight table, scaled x2 for Hermitian half-sum (x1 at the self-paired center)
// ---------------------------------------------------------------------------
__global__ void k_weights(const float* __restrict__ s0, const float* __restrict__ s1,
                          const float* __restrict__ a0, const float* __restrict__ a1)
{
    int idx = blockIdx.x * blockDim.x + threadIdx.x;
    if (idx >= HALF) return;
    int i = idx / MESH;
    int j = idx - i * MESH;
    float kx = (float)(i - KOFF);
    float ky = (float)(j - KOFF);
    float k2s = kx * kx + ky * ky;

    constexpr double PI_D  = 3.14159265358979323846;
    constexpr double TAU_D = 12.0 / (129.0 * 129.0);
    constexpr double MD    = 129.0;
    constexpr double PREF_D = (PI_D / TAU_D) * (PI_D / TAU_D) * 4.0 * PI_D
                            / (MD * MD * MD * MD * (2.0 * PI_D) * (2.0 * PI_D) * 2.0);
    constexpr float TAUF  = (float)TAU_D;
    constexpr float PREFF = (float)PREF_D;

    float f = (idx == HALF - 1) ? 1.0f : 2.0f;   // Hermitian pair factor
    float e = expf(2.0f * TAUF * k2s);
    float base = f * PREFF * e;
    float sh0 = s0[0], sh1 = s1[0];
    g_W[idx] = make_float2(base * a0[0] / (k2s + sh0 * sh0),
                           base * a1[0] / (k2s + sh1 * sh1));
}

// ---------------------------------------------------------------------------
// k1: closed-form 1D DFTs of the periodic spread Gaussian — pure fp32.
// A[p,k] = C * sum_{j=-1..1} e^{-tau m^2} e^{-i m x},  m = (k-64) + 129 j
// Phase done exactly: 2-product split + Cody-Waite 2pi reduction + __sincosf.
// ---------------------------------------------------------------------------
__global__ void k_ab(const float* __restrict__ x)
{
    int bp = blockIdx.x;
    float x0 = x[bp * 2 + 0];
    float x1 = x[bp * 2 + 1];

    constexpr float TAUF   = (float)(12.0 / (129.0 * 129.0));
    constexpr float INV2PI = 0.15915494309189535f;
    constexpr float PI2_HI = 6.28318548202514648f;   // fp32(2pi)
    constexpr float PI2_LO = -1.74845553e-7f;        // 2pi - fp32(2pi)
    const float Cst = 129.0f * sqrtf(12.566370614f * TAUF) * INV2PI;

    for (int t = threadIdx.x; t < 2 * MESH; t += blockDim.x) {
        int dim = (t >= MESH) ? 1 : 0;
        int k   = t - dim * MESH;
        float xx = dim ? x1 : x0;
        float kk = (float)(k - KOFF);

        float re = 0.0f, im = 0.0f;
        #pragma unroll
        for (int j = -1; j <= 1; j++) {
            float m = kk + (float)(MESH * j);
            float w = expf(-TAUF * m * m);
            float ph = m * xx;
            float pl = fmaf(m, xx, -ph);             // exact product residual
            float n  = rintf(ph * INV2PI);
            float r  = fmaf(n, -PI2_HI, ph);
            r = fmaf(n, -PI2_LO, r);
            r += pl;
            float s, c;
            __sincosf(r, &s, &c);
            re = fmaf(w, c, re);                     // e^{-imx} = cos - i sin
            im = fmaf(w, -s, im);
        }
        float2 v = make_float2(Cst * re, Cst * im);
        if (dim) g_B[bp * MESH + k] = v;
        else     g_A[bp * MESH + k] = v;
    }
}

// ---------------------------------------------------------------------------
// k2: partial T[pc,b,i,j] = sum_{p in chunk} A[p,i]*B[p,j], rows i in [0,65).
// 32x32 tile, 128 threads, 4x2 complex outputs per thread.
// ---------------------------------------------------------------------------
__global__ void k_T()
{
    __shared__ __align__(16) float2 At[32][32];
    __shared__ __align__(16) float2 Bt[32][32];

    int b  = blockIdx.z & 3;
    int pc = blockIdx.z >> 2;
    int i0 = blockIdx.y * 32;
    int j0 = blockIdx.x * 32;
    int tx = threadIdx.x;     // 0..15
    int ty = threadIdx.y;     // 0..7
    int tid = ty * 16 + tx;

    float accx[4][2], accy[4][2];
    #pragma unroll
    for (int r = 0; r < 4; r++)
        #pragma unroll
        for (int c = 0; c < 2; c++) { accx[r][c] = 0.0f; accy[r][c] = 0.0f; }

    const int pbase = b * NP + pc * (NP / PC);

    for (int p0 = 0; p0 < NP / PC; p0 += 32) {
        for (int l = tid; l < 32 * 32; l += 128) {
            int pp = l >> 5, ii = l & 31;
            int row = (pbase + p0 + pp) * MESH;
            int gi = i0 + ii, gj = j0 + ii;
            At[pp][ii] = (gi < MESH) ? g_A[row + gi] : make_float2(0.0f, 0.0f);
            Bt[pp][ii] = (gj < MESH) ? g_B[row + gj] : make_float2(0.0f, 0.0f);
        }
        __syncthreads();
        #pragma unroll 8
        for (int pp = 0; pp < 32; ++pp) {
            float4 a01 = *reinterpret_cast<const float4*>(&At[pp][ty * 4]);
            float4 a23 = *reinterpret_cast<const float4*>(&At[pp][ty * 4 + 2]);
            float4 bq  = *reinterpret_cast<const float4*>(&Bt[pp][tx * 2]);
            float ax[4] = {a01.x, a01.z, a23.x, a23.z};
            float ay[4] = {a01.y, a01.w, a23.y, a23.w};
            float bx[2] = {bq.x, bq.z};
            float by[2] = {bq.y, bq.w};
            #pragma unroll
            for (int r = 0; r < 4; r++)
                #pragma unroll
                for (int c = 0; c < 2; c++) {
                    accx[r][c] = fmaf(ax[r], bx[c], accx[r][c]);
                    accx[r][c] = fmaf(-ay[r], by[c], accx[r][c]);
                    accy[r][c] = fmaf(ax[r], by[c], accy[r][c]);
                    accy[r][c] = fmaf(ay[r], bx[c], accy[r][c]);
                }
        }
        __syncthreads();
    }

    #pragma unroll
    for (int r = 0; r < 4; r++) {
        int gi = i0 + ty * 4 + r;
        if (gi >= TROWS) continue;
        #pragma unroll
        for (int c = 0; c < 2; c++) {
            int gj = j0 + tx * 2 + c;
            if (gj < MESH)
                g_Tp[(pc * NB + b) * TN + gi * MESH + gj] =
                    make_float2(accx[r][c], accy[r][c]);
        }
    }
}

// ---------------------------------------------------------------------------
// k2b: reduce p-chunk partials and fuse with W into float4 table.
// ---------------------------------------------------------------------------
__global__ void k_Tred()
{
    int l = blockIdx.x * blockDim.x + threadIdx.x;
    if (l >= NB * TN) return;
    int b = l / TN, r = l - b * TN;
    float sx = 0.0f, sy = 0.0f;
    #pragma unroll
    for (int pc = 0; pc < PC; pc++) {
        float2 v = g_Tp[(pc * NB + b) * TN + r];
        sx += v.x; sy += v.y;
    }
    float2 w = (r < HALF) ? g_W[r] : make_float2(0.0f, 0.0f);
    g_TW[l] = make_float4(sx, sy, w.x, w.y);
}

// ---------------------------------------------------------------------------
// k3: E_c[b,p] = sum_{idx<HALF} W_c * ( Re(conj(S) T) - |S|^2 ),
//     S = A[p,k1]*B[p,k2] generated from shared-cached 1D factors.
//     Grid z splits modes; deterministic partials, no atomics.
// ---------------------------------------------------------------------------
__global__ void k_energy()
{
    __shared__ float2 As[PTS * TROWS];
    __shared__ float2 Bs[PTS * MESH];
    __shared__ float  red[16][8];

    int b  = blockIdx.y;
    int p0 = blockIdx.x * PTS;
    int z  = blockIdx.z;
    int tid = threadIdx.x;   // 256

    for (int l = tid; l < PTS * TROWS; l += 256) {
        int p = l / TROWS, k = l - p * TROWS;
        As[l] = g_A[(b * NP + p0 + p) * MESH + k];
    }
    for (int l = tid; l < PTS * MESH; l += 256) {
        int p = l / MESH, k = l - p * MESH;
        Bs[l] = g_B[(b * NP + p0 + p) * MESH + k];
    }
    __syncthreads();

    float e0[PTS], e1[PTS];
    #pragma unroll
    for (int p = 0; p < PTS; p++) { e0[p] = 0.0f; e1[p] = 0.0f; }

    const float4* __restrict__ TW = g_TW + b * TN;

    for (int idx = z * 256 + tid; idx < HALF; idx += 256 * NC) {
        int k1 = idx / MESH;
        int k2 = idx - k1 * MESH;
        float4 tw = __ldg(&TW[idx]);
        const float2* Ap = As + k1;
        const float2* Bp = Bs + k2;
        #pragma unroll
        for (int p = 0; p < PTS; p++) {
            float2 a  = Ap[p * TROWS];
            float2 bb = Bp[p * MESH];
            float sx = fmaf(a.x, bb.x, -a.y * bb.y);
            float sy = fmaf(a.x, bb.y,  a.y * bb.x);
            float v  = fmaf(sx, tw.x - sx, sy * (tw.y - sy));
            e0[p] = fmaf(tw.z, v, e0[p]);
            e1[p] = fmaf(tw.w, v, e1[p]);
        }
    }

    int lane = tid & 31, warp = tid >> 5;
    #pragma unroll
    for (int v = 0; v < 16; v++) {
        float val = (v & 1) ? e1[v >> 1] : e0[v >> 1];
        #pragma unroll
        for (int off = 16; off; off >>= 1)
            val += __shfl_down_sync(0xffffffffu, val, off);
        if (lane == 0) red[v][warp] = val;
    }
    __syncthreads();
    if (tid < 16) {
        float s = 0.0f;
        #pragma unroll
        for (int wq = 0; wq < 8; wq++) s += red[tid][wq];
        int p = tid >> 1, c = tid & 1;
        g_P[(z * BP + b * NP + p0 + p) * 2 + c] = s;
    }
}

// ---------------------------------------------------------------------------
// k4: final deterministic reduce of mode-chunk partials.
// ---------------------------------------------------------------------------
__global__ void k_reduce(float* __restrict__ out)
{
    int i = blockIdx.x * blockDim.x + threadIdx.x;
    if (i >= BP * 2) return;
    float s = 0.0f;
    #pragma unroll
    for (int z = 0; z < NC; z++) s += g_P[z * BP * 2 + i];
    out[i] = s;
}

// ---------------------------------------------------------------------------
extern "C" void kernel_launch(void* const* d_in, const int* in_sizes, int n_in,
                              void* d_out, int out_size)
{
    const float* x  = (const float*)d_in[0];
    const float* s0 = (const float*)d_in[1];
    const float* s1 = (const float*)d_in[2];
    const float* a0 = (const float*)d_in[3];
    const float* a1 = (const float*)d_in[4];

    k_weights<<<(HALF + 255) / 256, 256>>>(s0, s1, a0, a1);
    k_ab<<<BP, 256>>>(x);
    k_T<<<dim3((MESH + 31) / 32, (TROWS + 31) / 32, NB * PC), dim3(16, 8)>>>();
    k_Tred<<<(NB * TN + 255) / 256, 256>>>();
    k_energy<<<dim3(NP / PTS, NB, NC), 256>>>();
    k_reduce<<<(BP * 2 + 255) / 256, 256>>>((float*)d_out);
}

// round 3
// speedup vs baseline: 2.2365x; 1.0412x over previous
#include <cuda_runtime.h>
#include <math.h>

#define MESH  129
#define MM    (MESH*MESH)
#define NB    4
#define NP    512
#define BP    (NB*NP)            // 2048
#define KOFF  64
#define HALF  8321               // modes idx <= center; rest via Hermitian symmetry
#define TROWS 65
#define TN    (TROWS*MESH)       // 8385
#define PC    4                  // p-chunks in k_T
#define NC    2                  // mode chunks in k_energy
#define PTS   8                  // points per k_energy block (4 pairs)

typedef unsigned long long u64;

// ---- f32x2 packed helpers (Blackwell dual-fp32 datapath) ----
__device__ __forceinline__ u64 fma2(u64 a, u64 b, u64 c) {
    u64 d; asm("fma.rn.f32x2 %0, %1, %2, %3;" : "=l"(d) : "l"(a), "l"(b), "l"(c)); return d;
}
__device__ __forceinline__ u64 mul2(u64 a, u64 b) {
    u64 d; asm("mul.rn.f32x2 %0, %1, %2;" : "=l"(d) : "l"(a), "l"(b)); return d;
}
__device__ __forceinline__ u64 pack2(float lo, float hi) {
    u64 d; asm("mov.b64 %0, {%1, %2};" : "=l"(d) : "r"(__float_as_uint(lo)), "r"(__float_as_uint(hi))); return d;
}
__device__ __forceinline__ void unpack2(u64 v, float& lo, float& hi) {
    unsigned a, b; asm("mov.b64 {%0, %1}, %2;" : "=r"(a), "=r"(b) : "l"(v));
    lo = __uint_as_float(a); hi = __uint_as_float(b);
}

// Scratch (__device__ globals; no allocation allowed)
__device__ float2 g_A[BP*MESH];
__device__ float2 g_B[BP*MESH];
__device__ float2 g_Tp[PC*NB*TN];   // partial T per p-chunk
__device__ float4 g_TW[NB*TN];      // fused (T.re, T.im, w0, w1)
__device__ float  g_P[NC*BP*2];     // deterministic partial energies

// ---------------------------------------------------------------------------
// k1: closed-form 1D DFTs of the periodic spread Gaussian — pure fp32.
// ---------------------------------------------------------------------------
__global__ void k_ab(const float* __restrict__ x)
{
    int bp = blockIdx.x;
    float x0 = x[bp * 2 + 0];
    float x1 = x[bp * 2 + 1];

    constexpr float TAUF   = (float)(12.0 / (129.0 * 129.0));
    constexpr float INV2PI = 0.15915494309189535f;
    constexpr float PI2_HI = 6.28318548202514648f;
    constexpr float PI2_LO = -1.74845553e-7f;
    const float Cst = 129.0f * sqrtf(12.566370614f * TAUF) * INV2PI;

    for (int t = threadIdx.x; t < 2 * MESH; t += blockDim.x) {
        int dim = (t >= MESH) ? 1 : 0;
        int k   = t - dim * MESH;
        float xx = dim ? x1 : x0;
        float kk = (float)(k - KOFF);

        float re = 0.0f, im = 0.0f;
        #pragma unroll
        for (int j = -1; j <= 1; j++) {
            float m = kk + (float)(MESH * j);
            float w = expf(-TAUF * m * m);
            float ph = m * xx;
            float pl = fmaf(m, xx, -ph);
            float n  = rintf(ph * INV2PI);
            float r  = fmaf(n, -PI2_HI, ph);
            r = fmaf(n, -PI2_LO, r);
            r += pl;
            float s, c;
            __sincosf(r, &s, &c);
            re = fmaf(w, c, re);
            im = fmaf(w, -s, im);
        }
        float2 v = make_float2(Cst * re, Cst * im);
        if (dim) g_B[bp * MESH + k] = v;
        else     g_A[bp * MESH + k] = v;
    }
}

// ---------------------------------------------------------------------------
// k2: partial T[pc,b,i,j] = sum_p A[p,i]*B[p,j].  f32x2 across row pairs.
// 32x32 tile, 128 threads, 8 complex outputs/thread (4 rows x 2 cols).
// ---------------------------------------------------------------------------
__global__ void k_T()
{
    __shared__ float  sAx[32][32];
    __shared__ float  sAy[32][32];
    __shared__ float  sAn[32][32];
    __shared__ __align__(16) float2 sB[32][32];

    int b  = blockIdx.z & 3;
    int pc = blockIdx.z >> 2;
    int i0 = blockIdx.y * 32;
    int j0 = blockIdx.x * 32;
    int tx = threadIdx.x;     // 0..15
    int ty = threadIdx.y;     // 0..7
    int tid = ty * 16 + tx;

    u64 accx[2][2], accy[2][2];
    u64 Z = pack2(0.0f, 0.0f);
    #pragma unroll
    for (int q = 0; q < 2; q++)
        #pragma unroll
        for (int c = 0; c < 2; c++) { accx[q][c] = Z; accy[q][c] = Z; }

    const int pbase = b * NP + pc * (NP / PC);

    for (int p0 = 0; p0 < NP / PC; p0 += 32) {
        for (int l = tid; l < 32 * 32; l += 128) {
            int pp = l >> 5, ii = l & 31;
            int row = (pbase + p0 + pp) * MESH;
            int gi = i0 + ii, gj = j0 + ii;
            float2 a = (gi < MESH) ? g_A[row + gi] : make_float2(0.0f, 0.0f);
            sAx[pp][ii] = a.x;
            sAy[pp][ii] = a.y;
            sAn[pp][ii] = -a.y;
            sB[pp][ii]  = (gj < MESH) ? g_B[row + gj] : make_float2(0.0f, 0.0f);
        }
        __syncthreads();
        #pragma unroll 4
        for (int pp = 0; pp < 32; ++pp) {
            float4 bb = *reinterpret_cast<const float4*>(&sB[pp][tx * 2]);
            u64 bxb[2] = { pack2(bb.x, bb.x), pack2(bb.z, bb.z) };
            u64 byb[2] = { pack2(bb.y, bb.y), pack2(bb.w, bb.w) };
            #pragma unroll
            for (int q = 0; q < 2; q++) {
                u64 ax2 = *reinterpret_cast<const u64*>(&sAx[pp][ty * 4 + 2 * q]);
                u64 ay2 = *reinterpret_cast<const u64*>(&sAy[pp][ty * 4 + 2 * q]);
                u64 an2 = *reinterpret_cast<const u64*>(&sAn[pp][ty * 4 + 2 * q]);
                #pragma unroll
                for (int c = 0; c < 2; c++) {
                    accx[q][c] = fma2(ax2, bxb[c], accx[q][c]);
                    accx[q][c] = fma2(an2, byb[c], accx[q][c]);
                    accy[q][c] = fma2(ax2, byb[c], accy[q][c]);
                    accy[q][c] = fma2(ay2, bxb[c], accy[q][c]);
                }
            }
        }
        __syncthreads();
    }

    float2* Tp = g_Tp + (pc * NB + b) * TN;
    #pragma unroll
    for (int q = 0; q < 2; q++) {
        #pragma unroll
        for (int c = 0; c < 2; c++) {
            float x0, x1, y0, y1;
            unpack2(accx[q][c], x0, x1);
            unpack2(accy[q][c], y0, y1);
            int gj = j0 + tx * 2 + c;
            int gi = i0 + ty * 4 + 2 * q;
            if (gj < MESH) {
                if (gi     < TROWS) Tp[gi       * MESH + gj] = make_float2(x0, y0);
                if (gi + 1 < TROWS) Tp[(gi + 1) * MESH + gj] = make_float2(x1, y1);
            }
        }
    }
}

// ---------------------------------------------------------------------------
// k2b: reduce p-chunk partials + inline weight computation -> fused TW table.
// ---------------------------------------------------------------------------
__global__ void k_TW(const float* __restrict__ s0, const float* __restrict__ s1,
                     const float* __restrict__ a0, const float* __restrict__ a1)
{
    int l = blockIdx.x * blockDim.x + threadIdx.x;
    if (l >= NB * TN) return;
    int b = l / TN, r = l - b * TN;
    float sx = 0.0f, sy = 0.0f;
    #pragma unroll
    for (int pc = 0; pc < PC; pc++) {
        float2 v = g_Tp[(pc * NB + b) * TN + r];
        sx += v.x; sy += v.y;
    }
    float w0 = 0.0f, w1 = 0.0f;
    if (r < HALF) {
        int i = r / MESH;
        int j = r - i * MESH;
        float kx = (float)(i - KOFF);
        float ky = (float)(j - KOFF);
        float k2s = kx * kx + ky * ky;

        constexpr double PI_D  = 3.14159265358979323846;
        constexpr double TAU_D = 12.0 / (129.0 * 129.0);
        constexpr double MD    = 129.0;
        constexpr double PREF_D = (PI_D / TAU_D) * (PI_D / TAU_D) * 4.0 * PI_D
                                / (MD * MD * MD * MD * (2.0 * PI_D) * (2.0 * PI_D) * 2.0);
        constexpr float TAUF  = (float)TAU_D;
        constexpr float PREFF = (float)PREF_D;

        float f = (r == HALF - 1) ? 1.0f : 2.0f;
        float base = f * PREFF * expf(2.0f * TAUF * k2s);
        float sh0 = s0[0], sh1 = s1[0];
        w0 = base * a0[0] / (k2s + sh0 * sh0);
        w1 = base * a1[0] / (k2s + sh1 * sh1);
    }
    g_TW[l] = make_float4(sx, sy, w0, w1);
}

// ---------------------------------------------------------------------------
// k3: E_c[b,p] = sum_{idx<HALF} W_c * ( Re(conj(S)T) - |S|^2 ),
//     f32x2 across point pairs; SoA shared with pre-negated ay.
// ---------------------------------------------------------------------------
__global__ void k_energy()
{
    __shared__ __align__(8) float2 sAx[4][TROWS];
    __shared__ __align__(8) float2 sAy[4][TROWS];
    __shared__ __align__(8) float2 sAn[4][TROWS];
    __shared__ __align__(8) float2 sBx[4][MESH];
    __shared__ __align__(8) float2 sBy[4][MESH];
    __shared__ float red[16][8];

    int b  = blockIdx.y;
    int p0 = blockIdx.x * PTS;
    int z  = blockIdx.z;
    int tid = threadIdx.x;   // 256

    for (int l = tid; l < 4 * TROWS; l += 256) {
        int pp = l / TROWS, k = l - pp * TROWS;
        float2 v0 = g_A[(b * NP + p0 + 2 * pp)     * MESH + k];
        float2 v1 = g_A[(b * NP + p0 + 2 * pp + 1) * MESH + k];
        sAx[pp][k] = make_float2(v0.x, v1.x);
        sAy[pp][k] = make_float2(v0.y, v1.y);
        sAn[pp][k] = make_float2(-v0.y, -v1.y);
    }
    for (int l = tid; l < 4 * MESH; l += 256) {
        int pp = l / MESH, k = l - pp * MESH;
        float2 v0 = g_B[(b * NP + p0 + 2 * pp)     * MESH + k];
        float2 v1 = g_B[(b * NP + p0 + 2 * pp + 1) * MESH + k];
        sBx[pp][k] = make_float2(v0.x, v1.x);
        sBy[pp][k] = make_float2(v0.y, v1.y);
    }
    __syncthreads();

    u64 e0[4], e1[4];
    u64 Zr = pack2(0.0f, 0.0f);
    #pragma unroll
    for (int pp = 0; pp < 4; pp++) { e0[pp] = Zr; e1[pp] = Zr; }
    const u64 NEG1 = pack2(-1.0f, -1.0f);

    const float4* __restrict__ TW = g_TW + b * TN;

    int idx = z * 256 + tid;
    int k1 = idx / MESH;
    int k2 = idx - k1 * MESH;
    for (; idx < HALF; idx += 256 * NC) {
        float4 tw = __ldg(&TW[idx]);
        u64 tx2 = pack2(tw.x, tw.x);
        u64 ty2 = pack2(tw.y, tw.y);
        u64 w02 = pack2(tw.z, tw.z);
        u64 w12 = pack2(tw.w, tw.w);
        #pragma unroll
        for (int pp = 0; pp < 4; pp++) {
            u64 ax2 = *reinterpret_cast<const u64*>(&sAx[pp][k1]);
            u64 ay2 = *reinterpret_cast<const u64*>(&sAy[pp][k1]);
            u64 an2 = *reinterpret_cast<const u64*>(&sAn[pp][k1]);
            u64 bx2 = *reinterpret_cast<const u64*>(&sBx[pp][k2]);
            u64 by2 = *reinterpret_cast<const u64*>(&sBy[pp][k2]);
            u64 sx2 = fma2(ax2, bx2, mul2(an2, by2));
            u64 sy2 = fma2(ax2, by2, mul2(ay2, bx2));
            u64 r2  = fma2(sx2, tx2, mul2(sy2, ty2));
            u64 u2  = fma2(sy2, sy2, mul2(sx2, sx2));
            u64 v2  = fma2(u2, NEG1, r2);
            e0[pp] = fma2(w02, v2, e0[pp]);
            e1[pp] = fma2(w12, v2, e1[pp]);
        }
        // incremental (k1,k2) update: stride 512 = 3*129 + 125
        k1 += 3; k2 += 125;
        if (k2 >= MESH) { k2 -= MESH; k1 += 1; }
    }

    // unpack to 16 scalars: v = p*2 + c, p = 2*pp + hi/lo
    float ev[16];
    #pragma unroll
    for (int pp = 0; pp < 4; pp++) {
        float a, bq;
        unpack2(e0[pp], a, bq);
        ev[(2 * pp) * 2 + 0] = a;  ev[(2 * pp + 1) * 2 + 0] = bq;
        unpack2(e1[pp], a, bq);
        ev[(2 * pp) * 2 + 1] = a;  ev[(2 * pp + 1) * 2 + 1] = bq;
    }

    int lane = tid & 31, warp = tid >> 5;
    #pragma unroll
    for (int v = 0; v < 16; v++) {
        float val = ev[v];
        #pragma unroll
        for (int off = 16; off; off >>= 1)
            val += __shfl_down_sync(0xffffffffu, val, off);
        if (lane == 0) red[v][warp] = val;
    }
    __syncthreads();
    if (tid < 16) {
        float s = 0.0f;
        #pragma unroll
        for (int wq = 0; wq < 8; wq++) s += red[tid][wq];
        int p = tid >> 1, c = tid & 1;
        g_P[(z * BP + b * NP + p0 + p) * 2 + c] = s;
    }
}

// ---------------------------------------------------------------------------
// k4: final deterministic reduce of mode-chunk partials.
// ---------------------------------------------------------------------------
__global__ void k_reduce(float* __restrict__ out)
{
    int i = blockIdx.x * blockDim.x + threadIdx.x;
    if (i >= BP * 2) return;
    float s = g_P[i];
    #pragma unroll
    for (int z = 1; z < NC; z++) s += g_P[z * BP * 2 + i];
    out[i] = s;
}

// ---------------------------------------------------------------------------
extern "C" void kernel_launch(void* const* d_in, const int* in_sizes, int n_in,
                              void* d_out, int out_size)
{
    const float* x  = (const float*)d_in[0];
    const float* s0 = (const float*)d_in[1];
    const float* s1 = (const float*)d_in[2];
    const float* a0 = (const float*)d_in[3];
    const float* a1 = (const float*)d_in[4];

    k_ab<<<BP, 256>>>(x);
    k_T<<<dim3((MESH + 31) / 32, (TROWS + 31) / 32, NB * PC), dim3(16, 8)>>>();
    k_TW<<<(NB * TN + 255) / 256, 256>>>(s0, s1, a0, a1);
    k_energy<<<dim3(NP / PTS, NB, NC), 256>>>();
    k_reduce<<<(BP * 2 + 255) / 256, 256>>>((float*)d_out);
}

// round 4
// speedup vs baseline: 2.6949x; 1.2050x over previous
#include <cuda_runtime.h>
#include <math.h>

#define MESH  129
#define NB    4
#define NP    512
#define BP    2048
#define KOFF  64
#define HALF  8321               // modes idx <= center; rest via Hermitian symmetry
#define TROWS 65
#define TN    (TROWS*MESH)       // 8385
#define PC    8                  // p-chunks in k_T
#define PPTS  (NP/PC)            // 64 points per k_T block
#define ITILES 3
#define JTILES 5
#define NC    2                  // mode chunks in k_energy
#define PTS   8                  // points per k_energy block (4 packed pairs)

typedef unsigned long long u64;

// ---- f32x2 packed helpers (Blackwell dual-fp32 datapath) ----
__device__ __forceinline__ u64 fma2(u64 a, u64 b, u64 c) {
    u64 d; asm("fma.rn.f32x2 %0, %1, %2, %3;" : "=l"(d) : "l"(a), "l"(b), "l"(c)); return d;
}
__device__ __forceinline__ u64 mul2(u64 a, u64 b) {
    u64 d; asm("mul.rn.f32x2 %0, %1, %2;" : "=l"(d) : "l"(a), "l"(b)); return d;
}
__device__ __forceinline__ u64 pack2(float lo, float hi) {
    u64 d; asm("mov.b64 %0, {%1, %2};" : "=l"(d) : "r"(__float_as_uint(lo)), "r"(__float_as_uint(hi))); return d;
}
__device__ __forceinline__ void unpack2(u64 v, float& lo, float& hi) {
    unsigned a, b; asm("mov.b64 {%0, %1}, %2;" : "=r"(a), "=r"(b) : "l"(v));
    lo = __uint_as_float(a); hi = __uint_as_float(b);
}

// Scratch (__device__ globals; zero-initialized at load; no allocation allowed)
__device__ float2 g_Tp[PC*NB*TN];            // partial T per p-chunk
__device__ float4 g_TW[NB*TN];               // fused (T.re, T.im, w0, w1)
__device__ float  g_P[NC*BP*2];              // deterministic partial energies
__device__ int    g_cntT[NB*ITILES*JTILES];  // tail tickets (reset each launch)
__device__ int    g_cntE[NB*(NP/PTS)];

// ---------------------------------------------------------------------------
// Closed-form 1D DFT of the periodic spread Gaussian at frequency kk, point xx.
// F(kk) = C * sum_{j=-1..1} e^{-tau m^2} e^{-i m x},  m = kk + 129 j
// Pure fp32; exact phase via 2-product split + Cody-Waite 2pi reduction.
// ---------------------------------------------------------------------------
__device__ __forceinline__ float2 eval_dft(float kk, float xx)
{
    constexpr float TAUF   = (float)(12.0 / (129.0 * 129.0));
    constexpr float INV2PI = 0.15915494309189535f;
    constexpr float PI2_HI = 6.28318548202514648f;
    constexpr float PI2_LO = -1.74845553e-7f;
    const float Cst = 129.0f * sqrtf(12.566370614f * TAUF) * INV2PI;

    float re = 0.0f, im = 0.0f;
    #pragma unroll
    for (int j = -1; j <= 1; j++) {
        float m = kk + (float)(MESH * j);
        float w = expf(-TAUF * m * m);
        float ph = m * xx;
        float pl = fmaf(m, xx, -ph);
        float n  = rintf(ph * INV2PI);
        float r  = fmaf(n, -PI2_HI, ph);
        r = fmaf(n, -PI2_LO, r);
        r += pl;
        float s, c;
        __sincosf(r, &s, &c);
        re = fmaf(w, c, re);
        im = fmaf(w, -s, im);
    }
    return make_float2(Cst * re, Cst * im);
}

// ---------------------------------------------------------------------------
// Kernel A: partial T[pc,b,i,j] = sum_p A[p,i]*B[p,j] with in-kernel A/B gen.
// 32x32 tile, 128 threads, 8 complex outputs/thread. Tail block (last of PC
// per tile) reduces partials + computes weights -> g_TW.
// ---------------------------------------------------------------------------
__global__ void __launch_bounds__(128) k_T(
    const float* __restrict__ x,
    const float* __restrict__ s0, const float* __restrict__ s1,
    const float* __restrict__ a0, const float* __restrict__ a1)
{
    __shared__ __align__(16) float sAx[PPTS][32];
    __shared__ __align__(16) float sAy[PPTS][32];
    __shared__ __align__(16) float sAn[PPTS][32];
    __shared__ __align__(16) float sBx[PPTS][32];
    __shared__ __align__(16) float sBy[PPTS][32];
    __shared__ float sx0[PPTS], sx1[PPTS];
    __shared__ int s_ticket;

    int b  = blockIdx.z & 3;
    int pc = blockIdx.z >> 2;
    int i0 = blockIdx.y * 32;
    int j0 = blockIdx.x * 32;
    int tid = threadIdx.x;          // 128
    int tx = tid & 15, ty = tid >> 4;

    const int pbase = b * NP + pc * PPTS;

    if (tid < PPTS) {
        sx0[tid] = x[(pbase + tid) * 2 + 0];
        sx1[tid] = x[(pbase + tid) * 2 + 1];
    }
    __syncthreads();

    // Generate A (i-tile) and B (j-tile) factors for 64 points into shared.
    for (int l = tid; l < PPTS * 32; l += 128) {
        int pt = l >> 5, ii = l & 31;
        int gi = i0 + ii, gj = j0 + ii;
        float2 a = (gi < TROWS) ? eval_dft((float)(gi - KOFF), sx0[pt])
                                : make_float2(0.0f, 0.0f);
        float2 bb = (gj < MESH) ? eval_dft((float)(gj - KOFF), sx1[pt])
                                : make_float2(0.0f, 0.0f);
        sAx[pt][ii] = a.x; sAy[pt][ii] = a.y; sAn[pt][ii] = -a.y;
        sBx[pt][ii] = bb.x; sBy[pt][ii] = bb.y;
    }
    __syncthreads();

    u64 accx[2][2], accy[2][2];
    u64 Z = pack2(0.0f, 0.0f);
    #pragma unroll
    for (int q = 0; q < 2; q++)
        #pragma unroll
        for (int c = 0; c < 2; c++) { accx[q][c] = Z; accy[q][c] = Z; }

    #pragma unroll 4
    for (int pp = 0; pp < PPTS; ++pp) {
        float2 bxv = *reinterpret_cast<const float2*>(&sBx[pp][tx * 2]);
        float2 byv = *reinterpret_cast<const float2*>(&sBy[pp][tx * 2]);
        u64 bxb[2] = { pack2(bxv.x, bxv.x), pack2(bxv.y, bxv.y) };
        u64 byb[2] = { pack2(byv.x, byv.x), pack2(byv.y, byv.y) };
        float4 qax = *reinterpret_cast<const float4*>(&sAx[pp][ty * 4]);
        float4 qay = *reinterpret_cast<const float4*>(&sAy[pp][ty * 4]);
        float4 qan = *reinterpret_cast<const float4*>(&sAn[pp][ty * 4]);
        u64 ax2[2] = { pack2(qax.x, qax.y), pack2(qax.z, qax.w) };
        u64 ay2[2] = { pack2(qay.x, qay.y), pack2(qay.z, qay.w) };
        u64 an2[2] = { pack2(qan.x, qan.y), pack2(qan.z, qan.w) };
        #pragma unroll
        for (int q = 0; q < 2; q++) {
            #pragma unroll
            for (int c = 0; c < 2; c++) {
                accx[q][c] = fma2(ax2[q], bxb[c], accx[q][c]);
                accx[q][c] = fma2(an2[q], byb[c], accx[q][c]);
                accy[q][c] = fma2(ax2[q], byb[c], accy[q][c]);
                accy[q][c] = fma2(ay2[q], bxb[c], accy[q][c]);
            }
        }
    }

    float2* Tp = g_Tp + (pc * NB + b) * TN;
    #pragma unroll
    for (int q = 0; q < 2; q++) {
        #pragma unroll
        for (int c = 0; c < 2; c++) {
            float v0, v1, w0, w1;
            unpack2(accx[q][c], v0, v1);
            unpack2(accy[q][c], w0, w1);
            int gj = j0 + tx * 2 + c;
            int gi = i0 + ty * 4 + 2 * q;
            if (gj < MESH) {
                if (gi     < TROWS) Tp[gi       * MESH + gj] = make_float2(v0, w0);
                if (gi + 1 < TROWS) Tp[(gi + 1) * MESH + gj] = make_float2(v1, w1);
            }
        }
    }

    // ---- tail: last of the PC blocks for this (b, tile) fuses TW ----
    __threadfence();
    int cidx = (b * ITILES + blockIdx.y) * JTILES + blockIdx.x;
    if (tid == 0) s_ticket = atomicAdd(&g_cntT[cidx], 1);
    __syncthreads();
    if (s_ticket == PC - 1) {
        int rows = TROWS - i0; if (rows > 32) rows = 32;
        for (int l = tid; l < rows * 32; l += 128) {
            int r = l >> 5, c = l & 31;
            int gi = i0 + r, gj = j0 + c;
            if (gj >= MESH) continue;
            int off = gi * MESH + gj;
            float tsx = 0.0f, tsy = 0.0f;
            #pragma unroll
            for (int p2 = 0; p2 < PC; p2++) {
                float2 v = __ldcg(&g_Tp[(p2 * NB + b) * TN + off]);
                tsx += v.x; tsy += v.y;
            }
            float w0 = 0.0f, w1 = 0.0f;
            if (off < HALF) {
                float kx = (float)(gi - KOFF);
                float ky = (float)(gj - KOFF);
                float k2s = kx * kx + ky * ky;
                constexpr double PI_D  = 3.14159265358979323846;
                constexpr double TAU_D = 12.0 / (129.0 * 129.0);
                constexpr double MD    = 129.0;
                constexpr double PREF_D = (PI_D / TAU_D) * (PI_D / TAU_D) * 4.0 * PI_D
                                        / (MD*MD*MD*MD * (2.0*PI_D) * (2.0*PI_D) * 2.0);
                float f = (off == HALF - 1) ? 1.0f : 2.0f;
                float base = f * (float)PREF_D * expf(2.0f * (float)TAU_D * k2s);
                float sh0 = s0[0], sh1 = s1[0];
                w0 = base * a0[0] / (k2s + sh0 * sh0);
                w1 = base * a1[0] / (k2s + sh1 * sh1);
            }
            g_TW[b * TN + off] = make_float4(tsx, tsy, w0, w1);
        }
        if (tid == 0) g_cntT[cidx] = 0;   // reset for next graph replay
    }
}

// ---------------------------------------------------------------------------
// Kernel B: E_c[b,p] = sum_{idx<HALF} W_c * ( Re(conj(S)T) - |S|^2 ),
// S = A[p,k1]*B[p,k2] generated in-kernel. f32x2 across point pairs.
// Tail block (last of NC per point-group) reduces partials -> out.
// ---------------------------------------------------------------------------
__global__ void __launch_bounds__(256) k_energy(
    const float* __restrict__ x, float* __restrict__ out)
{
    __shared__ __align__(16) float sAx[TROWS][8];
    __shared__ __align__(16) float sAy[TROWS][8];
    __shared__ __align__(16) float sAn[TROWS][8];
    __shared__ __align__(8)  float2 sBx[4][MESH];
    __shared__ __align__(8)  float2 sBy[4][MESH];
    __shared__ float red[16][8];
    __shared__ float sxp[PTS][2];
    __shared__ int s_ticket;

    int b  = blockIdx.y;
    int p0 = blockIdx.x * PTS;
    int z  = blockIdx.z;
    int tid = threadIdx.x;   // 256

    if (tid < PTS * 2)
        sxp[tid >> 1][tid & 1] = x[(b * NP + p0 + (tid >> 1)) * 2 + (tid & 1)];
    __syncthreads();

    for (int l = tid; l < PTS * TROWS; l += 256) {
        int pt = l / TROWS, k = l - pt * TROWS;
        float2 a = eval_dft((float)(k - KOFF), sxp[pt][0]);
        sAx[k][pt] = a.x; sAy[k][pt] = a.y; sAn[k][pt] = -a.y;
    }
    for (int l = tid; l < PTS * MESH; l += 256) {
        int pt = l / MESH, k = l - pt * MESH;
        float2 bb = eval_dft((float)(k - KOFF), sxp[pt][1]);
        reinterpret_cast<float*>(&sBx[pt >> 1][k])[pt & 1] = bb.x;
        reinterpret_cast<float*>(&sBy[pt >> 1][k])[pt & 1] = bb.y;
    }
    __syncthreads();

    u64 e0[4], e1[4];
    u64 Zr = pack2(0.0f, 0.0f);
    #pragma unroll
    for (int pr = 0; pr < 4; pr++) { e0[pr] = Zr; e1[pr] = Zr; }
    const u64 NEG1 = pack2(-1.0f, -1.0f);

    const float4* __restrict__ TW = g_TW + b * TN;

    int idx = z * 256 + tid;
    int k1 = idx / MESH;
    int k2 = idx - k1 * MESH;
    for (; idx < HALF; idx += 256 * NC) {
        float4 tw = __ldg(&TW[idx]);
        u64 tx2 = pack2(tw.x, tw.x);
        u64 ty2 = pack2(tw.y, tw.y);
        u64 w02 = pack2(tw.z, tw.z);
        u64 w12 = pack2(tw.w, tw.w);

        float4 qx0 = *reinterpret_cast<const float4*>(&sAx[k1][0]);
        float4 qx1 = *reinterpret_cast<const float4*>(&sAx[k1][4]);
        float4 qy0 = *reinterpret_cast<const float4*>(&sAy[k1][0]);
        float4 qy1 = *reinterpret_cast<const float4*>(&sAy[k1][4]);
        float4 qn0 = *reinterpret_cast<const float4*>(&sAn[k1][0]);
        float4 qn1 = *reinterpret_cast<const float4*>(&sAn[k1][4]);
        u64 ax[4] = { pack2(qx0.x,qx0.y), pack2(qx0.z,qx0.w), pack2(qx1.x,qx1.y), pack2(qx1.z,qx1.w) };
        u64 ay[4] = { pack2(qy0.x,qy0.y), pack2(qy0.z,qy0.w), pack2(qy1.x,qy1.y), pack2(qy1.z,qy1.w) };
        u64 an[4] = { pack2(qn0.x,qn0.y), pack2(qn0.z,qn0.w), pack2(qn1.x,qn1.y), pack2(qn1.z,qn1.w) };

        #pragma unroll
        for (int pr = 0; pr < 4; pr++) {
            u64 bx2 = *reinterpret_cast<const u64*>(&sBx[pr][k2]);
            u64 by2 = *reinterpret_cast<const u64*>(&sBy[pr][k2]);
            u64 sx2 = fma2(ax[pr], bx2, mul2(an[pr], by2));
            u64 sy2 = fma2(ax[pr], by2, mul2(ay[pr], bx2));
            u64 dx2 = fma2(sx2, NEG1, tx2);
            u64 dy2 = fma2(sy2, NEG1, ty2);
            u64 v2  = fma2(sx2, dx2, mul2(sy2, dy2));
            e0[pr] = fma2(w02, v2, e0[pr]);
            e1[pr] = fma2(w12, v2, e1[pr]);
        }
        k1 += 3; k2 += 125;                 // stride 512 = 3*129 + 125
        if (k2 >= MESH) { k2 -= MESH; k1 += 1; }
    }

    float ev[16];
    #pragma unroll
    for (int pr = 0; pr < 4; pr++) {
        float a, bq;
        unpack2(e0[pr], a, bq);
        ev[(2 * pr) * 2 + 0] = a;  ev[(2 * pr + 1) * 2 + 0] = bq;
        unpack2(e1[pr], a, bq);
        ev[(2 * pr) * 2 + 1] = a;  ev[(2 * pr + 1) * 2 + 1] = bq;
    }

    int lane = tid & 31, warp = tid >> 5;
    #pragma unroll
    for (int v = 0; v < 16; v++) {
        float val = ev[v];
        #pragma unroll
        for (int off = 16; off; off >>= 1)
            val += __shfl_down_sync(0xffffffffu, val, off);
        if (lane == 0) red[v][warp] = val;
    }
    __syncthreads();
    if (tid < 16) {
        float s = 0.0f;
        #pragma unroll
        for (int wq = 0; wq < 8; wq++) s += red[tid][wq];
        int p = tid >> 1, c = tid & 1;
        g_P[(z * BP + b * NP + p0 + p) * 2 + c] = s;
    }

    // ---- tail: last of NC blocks for this (b, p0) writes final output ----
    __threadfence();
    int cidx = b * (NP / PTS) + blockIdx.x;
    if (tid == 0) s_ticket = atomicAdd(&g_cntE[cidx], 1);
    __syncthreads();
    if (s_ticket == NC - 1) {
        if (tid < 16) {
            int p = tid >> 1, c = tid & 1;
            int o = (b * NP + p0 + p) * 2 + c;
            float s = 0.0f;
            #pragma unroll
            for (int z2 = 0; z2 < NC; z2++) s += __ldcg(&g_P[z2 * BP * 2 + o]);
            out[o] = s;
        }
        if (tid == 0) g_cntE[cidx] = 0;    // reset for next graph replay
    }
}

// ---------------------------------------------------------------------------
extern "C" void kernel_launch(void* const* d_in, const int* in_sizes, int n_in,
                              void* d_out, int out_size)
{
    const float* x  = (const float*)d_in[0];
    const float* s0 = (const float*)d_in[1];
    const float* s1 = (const float*)d_in[2];
    const float* a0 = (const float*)d_in[3];
    const float* a1 = (const float*)d_in[4];

    k_T<<<dim3(JTILES, ITILES, NB * PC), 128>>>(x, s0, s1, a0, a1);
    k_energy<<<dim3(NP / PTS, NB, NC), 256>>>(x, (float*)d_out);
}

// round 5
// speedup vs baseline: 2.8174x; 1.0455x over previous
#include <cuda_runtime.h>
#include <math.h>

#define MESH  129
#define NB    4
#define NP    512
#define BP    2048
#define KOFF  64
#define HALF  8321               // modes idx <= center; rest via Hermitian symmetry
#define TROWS 65
#define TN    (TROWS*MESH)       // 8385
#define PC    8                  // p-chunks in k_T
#define PPTS  (NP/PC)            // 64 points per k_T block
#define TI    36                 // k_T i-tile rows
#define TJ    26                 // k_T j-tile cols
#define ITILES 2
#define JTILES 5
#define NTHR_T 117               // 13 x 9
#define NC    2                  // mode chunks in k_energy
#define PTS   16                 // points per k_energy block (8 packed pairs)
#define BPAD  18                 // padded pair-row stride (floats) in k_energy shared

typedef unsigned long long u64;

// ---- f32x2 packed helpers ----
__device__ __forceinline__ u64 fma2(u64 a, u64 b, u64 c) {
    u64 d; asm("fma.rn.f32x2 %0, %1, %2, %3;" : "=l"(d) : "l"(a), "l"(b), "l"(c)); return d;
}
__device__ __forceinline__ u64 mul2(u64 a, u64 b) {
    u64 d; asm("mul.rn.f32x2 %0, %1, %2;" : "=l"(d) : "l"(a), "l"(b)); return d;
}
__device__ __forceinline__ u64 pack2(float lo, float hi) {
    u64 d; asm("mov.b64 %0, {%1, %2};" : "=l"(d) : "r"(__float_as_uint(lo)), "r"(__float_as_uint(hi))); return d;
}
__device__ __forceinline__ void unpack2(u64 v, float& lo, float& hi) {
    unsigned a, b; asm("mov.b64 {%0, %1}, %2;" : "=r"(a), "=r"(b) : "l"(v));
    lo = __uint_as_float(a); hi = __uint_as_float(b);
}

// Scratch (__device__ globals; zero-initialized; no allocation allowed)
__device__ float2 g_Tp[PC*NB*TN];
__device__ float4 g_TW[NB*TN];
__device__ float  g_P[NC*BP*2];
__device__ int    g_cntT[NB*ITILES*JTILES];
__device__ int    g_cntE[NB*(NP/PTS)];

// ---- constants ----
#define TAUF   ((float)(12.0 / (129.0 * 129.0)))
#define T258   (258.0f * TAUF)
#define KC     6.144212353e-6f          /* e^{-129^2 * tau} = e^{-12} */
#define INV2PI 0.15915494309189535f
#define PI2_HI 6.28318548202514648f
#define PI2_LO (-1.74845553e-7f)

// cos/sin of (m*xx) with exact-product + Cody-Waite 2pi reduction
__device__ __forceinline__ float2 sincos_red(float m, float xx)
{
    float ph = m * xx;
    float pl = fmaf(m, xx, -ph);
    float n  = rintf(ph * INV2PI);
    float r  = fmaf(n, -PI2_HI, ph);
    r = fmaf(n, -PI2_LO, r);
    r += pl;
    float s, c;
    __sincosf(r, &s, &c);
    return make_float2(c, s);
}

// Fast closed-form 1D DFT of periodic spread Gaussian (5 MUFU):
// F(kk) = Cst * sum_{j=-1..1} e^{-tau (kk+129j)^2} e^{-i (kk+129j) x}
// with e^{-tau(kk±129)^2} = E * D^{±1} * KC and e^{-i(kk±129)x} = base * e^{∓i129x}.
// (rc, rs) = (cos(129x), sin(129x)).
__device__ __forceinline__ float2 eval_fast(float kk, float xx, float rc, float rs)
{
    const float Cst = 129.0f * sqrtf(12.566370614f * TAUF) * INV2PI;
    float E  = __expf(-TAUF * kk * kk) * Cst;
    float D  = __expf(-T258 * kk);
    float Di = __fdividef(1.0f, D);
    float ep = D * KC, em = Di * KC;
    float2 cs = sincos_red(kk, xx);
    float bc = cs.x, bs = -cs.y;                  // base = e^{-i kk x}
    float tpre = fmaf(bc, rc,  bs * rs);          // base * (rc,-rs)
    float tpim = fmaf(bs, rc, -bc * rs);
    float tmre = fmaf(bc, rc, -bs * rs);          // base * (rc,+rs)
    float tmim = fmaf(bc, rs,  bs * rc);
    float re = fmaf(ep, tpre, fmaf(em, tmre, bc));
    float im = fmaf(ep, tpim, fmaf(em, tmim, bs));
    return make_float2(E * re, E * im);
}

// ---------------------------------------------------------------------------
// Kernel A: partial T[pc,b,i,j] = sum_p A[p,i]*B[p,j]; 36x26 tiles, 117 thr.
// Tail block (last of PC per tile) reduces partials + weights -> g_TW.
// ---------------------------------------------------------------------------
__global__ void __launch_bounds__(NTHR_T) k_T(
    const float* __restrict__ x,
    const float* __restrict__ s0, const float* __restrict__ s1,
    const float* __restrict__ a0, const float* __restrict__ a1)
{
    __shared__ float sAx[PPTS][TI];
    __shared__ float sAy[PPTS][TI];
    __shared__ float sBx[PPTS][TJ];
    __shared__ float sBy[PPTS][TJ];
    __shared__ float sxp[PPTS][2];
    __shared__ float srot[PPTS][2][2];   // [pt][dim][cos,sin] of 129*x
    __shared__ int s_ticket;

    int b  = blockIdx.z & 3;
    int pc = blockIdx.z >> 2;
    int i0 = blockIdx.y * TI;
    int j0 = blockIdx.x * TJ;
    int tid = threadIdx.x;             // 0..116
    int tx = tid % 13, ty = tid / 13;  // 13 x 9

    const int pbase = b * NP + pc * PPTS;

    for (int l = tid; l < PPTS * 2; l += NTHR_T)
        sxp[l >> 1][l & 1] = x[(pbase + (l >> 1)) * 2 + (l & 1)];
    __syncthreads();
    for (int l = tid; l < PPTS * 2; l += NTHR_T) {
        float2 cs = sincos_red(129.0f, sxp[l >> 1][l & 1]);
        srot[l >> 1][l & 1][0] = cs.x;
        srot[l >> 1][l & 1][1] = cs.y;
    }
    __syncthreads();

    // Generate A (TI rows from i0) and B (TJ cols from j0) factors.
    for (int l = tid; l < PPTS * (TI + TJ); l += NTHR_T) {
        if (l < PPTS * TI) {
            int pt = l / TI, ii = l - pt * TI;
            int gi = i0 + ii;
            float2 a = make_float2(0.0f, 0.0f);
            if (gi < TROWS)
                a = eval_fast((float)(gi - KOFF), sxp[pt][0], srot[pt][0][0], srot[pt][0][1]);
            sAx[pt][ii] = a.x; sAy[pt][ii] = a.y;
        } else {
            int l2 = l - PPTS * TI;
            int pt = l2 / TJ, jj = l2 - pt * TJ;
            int gj = j0 + jj;
            float2 bb = make_float2(0.0f, 0.0f);
            if (gj < MESH)
                bb = eval_fast((float)(gj - KOFF), sxp[pt][1], srot[pt][1][0], srot[pt][1][1]);
            sBx[pt][jj] = bb.x; sBy[pt][jj] = bb.y;
        }
    }
    __syncthreads();

    u64 accx[2][2], accy[2][2];
    u64 Z = pack2(0.0f, 0.0f);
    #pragma unroll
    for (int q = 0; q < 2; q++)
        #pragma unroll
        for (int c = 0; c < 2; c++) { accx[q][c] = Z; accy[q][c] = Z; }

    const u64 SGN = 0x8000000080000000ULL;

    #pragma unroll 4
    for (int pp = 0; pp < PPTS; ++pp) {
        float2 bxv = *reinterpret_cast<const float2*>(&sBx[pp][tx * 2]);
        float2 byv = *reinterpret_cast<const float2*>(&sBy[pp][tx * 2]);
        u64 bxb[2] = { pack2(bxv.x, bxv.x), pack2(bxv.y, bxv.y) };
        u64 byb[2] = { pack2(byv.x, byv.x), pack2(byv.y, byv.y) };
        #pragma unroll
        for (int q = 0; q < 2; q++) {
            u64 ax2 = *reinterpret_cast<const u64*>(&sAx[pp][ty * 4 + 2 * q]);
            u64 ay2 = *reinterpret_cast<const u64*>(&sAy[pp][ty * 4 + 2 * q]);
            u64 an2 = ay2 ^ SGN;
            #pragma unroll
            for (int c = 0; c < 2; c++) {
                accx[q][c] = fma2(ax2, bxb[c], accx[q][c]);
                accx[q][c] = fma2(an2, byb[c], accx[q][c]);
                accy[q][c] = fma2(ax2, byb[c], accy[q][c]);
                accy[q][c] = fma2(ay2, bxb[c], accy[q][c]);
            }
        }
    }

    float2* Tp = g_Tp + (pc * NB + b) * TN;
    #pragma unroll
    for (int q = 0; q < 2; q++) {
        #pragma unroll
        for (int c = 0; c < 2; c++) {
            float v0, v1, w0, w1;
            unpack2(accx[q][c], v0, v1);
            unpack2(accy[q][c], w0, w1);
            int gj = j0 + tx * 2 + c;
            int gi = i0 + ty * 4 + 2 * q;
            if (gj < MESH) {
                if (gi     < TROWS) Tp[gi       * MESH + gj] = make_float2(v0, w0);
                if (gi + 1 < TROWS) Tp[(gi + 1) * MESH + gj] = make_float2(v1, w1);
            }
        }
    }

    // ---- tail: last of the PC blocks for this (b, tile) fuses TW ----
    __threadfence();
    int cidx = (b * ITILES + blockIdx.y) * JTILES + blockIdx.x;
    if (tid == 0) s_ticket = atomicAdd(&g_cntT[cidx], 1);
    __syncthreads();
    if (s_ticket == PC - 1) {
        int rows = TROWS - i0; if (rows > TI) rows = TI;
        for (int l = tid; l < rows * TJ; l += NTHR_T) {
            int r = l / TJ, c = l - r * TJ;
            int gi = i0 + r, gj = j0 + c;
            if (gj >= MESH) continue;
            int off = gi * MESH + gj;
            float tsx = 0.0f, tsy = 0.0f;
            #pragma unroll
            for (int p2 = 0; p2 < PC; p2++) {
                float2 v = __ldcg(&g_Tp[(p2 * NB + b) * TN + off]);
                tsx += v.x; tsy += v.y;
            }
            float w0 = 0.0f, w1 = 0.0f;
            if (off < HALF) {
                float kx = (float)(gi - KOFF);
                float ky = (float)(gj - KOFF);
                float k2s = kx * kx + ky * ky;
                constexpr double PI_D  = 3.14159265358979323846;
                constexpr double TAU_D = 12.0 / (129.0 * 129.0);
                constexpr double MD    = 129.0;
                constexpr double PREF_D = (PI_D / TAU_D) * (PI_D / TAU_D) * 4.0 * PI_D
                                        / (MD*MD*MD*MD * (2.0*PI_D) * (2.0*PI_D) * 2.0);
                float f = (off == HALF - 1) ? 1.0f : 2.0f;
                float base = f * (float)PREF_D * expf(2.0f * (float)TAU_D * k2s);
                float sh0 = s0[0], sh1 = s1[0];
                w0 = base * a0[0] / (k2s + sh0 * sh0);
                w1 = base * a1[0] / (k2s + sh1 * sh1);
            }
            g_TW[b * TN + off] = make_float4(tsx, tsy, w0, w1);
        }
        if (tid == 0) g_cntT[cidx] = 0;
    }
}

// ---------------------------------------------------------------------------
// Kernel B: E_c[b,p] = sum_{idx<HALF} W_c * ( Re(conj(S)T) - |S|^2 ).
// 16 points/block (8 packed pairs), pair-major shared with stride-18 pad.
// ---------------------------------------------------------------------------
__global__ void __launch_bounds__(256) k_energy(
    const float* __restrict__ x, float* __restrict__ out)
{
    __shared__ float sAx[TROWS][BPAD];
    __shared__ float sAy[TROWS][BPAD];
    __shared__ float sBx[MESH][BPAD];
    __shared__ float sBy[MESH][BPAD];
    __shared__ float red[32][8];
    __shared__ float sxp[PTS][2];
    __shared__ float srot[PTS][2][2];
    __shared__ int s_ticket;

    int b  = blockIdx.y;
    int p0 = blockIdx.x * PTS;
    int z  = blockIdx.z;
    int tid = threadIdx.x;   // 256

    if (tid < PTS * 2)
        sxp[tid >> 1][tid & 1] = x[(b * NP + p0 + (tid >> 1)) * 2 + (tid & 1)];
    __syncthreads();
    if (tid < PTS * 2) {
        float2 cs = sincos_red(129.0f, sxp[tid >> 1][tid & 1]);
        srot[tid >> 1][tid & 1][0] = cs.x;
        srot[tid >> 1][tid & 1][1] = cs.y;
    }
    __syncthreads();

    for (int l = tid; l < PTS * TROWS; l += 256) {
        int pt = l & (PTS - 1), k = l >> 4;
        float2 a = eval_fast((float)(k - KOFF), sxp[pt][0], srot[pt][0][0], srot[pt][0][1]);
        sAx[k][pt] = a.x; sAy[k][pt] = a.y;
    }
    for (int l = tid; l < PTS * MESH; l += 256) {
        int pt = l & (PTS - 1), k = l >> 4;
        float2 bb = eval_fast((float)(k - KOFF), sxp[pt][1], srot[pt][1][0], srot[pt][1][1]);
        sBx[k][pt] = bb.x; sBy[k][pt] = bb.y;
    }
    __syncthreads();

    u64 e0[8], e1[8];
    u64 Zr = pack2(0.0f, 0.0f);
    #pragma unroll
    for (int pr = 0; pr < 8; pr++) { e0[pr] = Zr; e1[pr] = Zr; }
    const u64 NEG1 = pack2(-1.0f, -1.0f);
    const u64 SGN  = 0x8000000080000000ULL;

    const float4* __restrict__ TW = g_TW + b * TN;

    int idx = z * 256 + tid;
    int k1 = idx / MESH;
    int k2 = idx - k1 * MESH;
    for (; idx < HALF; idx += 256 * NC) {
        float4 tw = __ldg(&TW[idx]);
        u64 tx2 = pack2(tw.x, tw.x);
        u64 ty2 = pack2(tw.y, tw.y);
        u64 w02 = pack2(tw.z, tw.z);
        u64 w12 = pack2(tw.w, tw.w);
        #pragma unroll
        for (int pr = 0; pr < 8; pr++) {
            u64 ax2 = *reinterpret_cast<const u64*>(&sAx[k1][2 * pr]);
            u64 ay2 = *reinterpret_cast<const u64*>(&sAy[k1][2 * pr]);
            u64 bx2 = *reinterpret_cast<const u64*>(&sBx[k2][2 * pr]);
            u64 by2 = *reinterpret_cast<const u64*>(&sBy[k2][2 * pr]);
            u64 an2 = ay2 ^ SGN;
            u64 sx2 = fma2(ax2, bx2, mul2(an2, by2));
            u64 sy2 = fma2(ax2, by2, mul2(ay2, bx2));
            u64 dx2 = fma2(sx2, NEG1, tx2);
            u64 dy2 = fma2(sy2, NEG1, ty2);
            u64 v2  = fma2(sx2, dx2, mul2(sy2, dy2));
            e0[pr] = fma2(w02, v2, e0[pr]);
            e1[pr] = fma2(w12, v2, e1[pr]);
        }
        k1 += 3; k2 += 125;                 // stride 512 = 3*129 + 125
        if (k2 >= MESH) { k2 -= MESH; k1 += 1; }
    }

    float ev[32];
    #pragma unroll
    for (int pr = 0; pr < 8; pr++) {
        float a, bq;
        unpack2(e0[pr], a, bq);
        ev[(2 * pr) * 2 + 0] = a;  ev[(2 * pr + 1) * 2 + 0] = bq;
        unpack2(e1[pr], a, bq);
        ev[(2 * pr) * 2 + 1] = a;  ev[(2 * pr + 1) * 2 + 1] = bq;
    }

    int lane = tid & 31, warp = tid >> 5;
    #pragma unroll
    for (int v = 0; v < 32; v++) {
        float val = ev[v];
        #pragma unroll
        for (int off = 16; off; off >>= 1)
            val += __shfl_down_sync(0xffffffffu, val, off);
        if (lane == 0) red[v][warp] = val;
    }
    __syncthreads();
    if (tid < 32) {
        float s = 0.0f;
        #pragma unroll
        for (int wq = 0; wq < 8; wq++) s += red[tid][wq];
        int p = tid >> 1, c = tid & 1;
        g_P[(z * BP + b * NP + p0 + p) * 2 + c] = s;
    }

    // ---- tail: last of NC blocks for this (b, p0) writes final output ----
    __threadfence();
    int cidx = b * (NP / PTS) + blockIdx.x;
    if (tid == 0) s_ticket = atomicAdd(&g_cntE[cidx], 1);
    __syncthreads();
    if (s_ticket == NC - 1) {
        if (tid < 32) {
            int p = tid >> 1, c = tid & 1;
            int o = (b * NP + p0 + p) * 2 + c;
            float s = 0.0f;
            #pragma unroll
            for (int z2 = 0; z2 < NC; z2++) s += __ldcg(&g_P[z2 * BP * 2 + o]);
            out[o] = s;
        }
        if (tid == 0) g_cntE[cidx] = 0;
    }
}

// ---------------------------------------------------------------------------
extern "C" void kernel_launch(void* const* d_in, const int* in_sizes, int n_in,
                              void* d_out, int out_size)
{
    const float* x  = (const float*)d_in[0];
    const float* s0 = (const float*)d_in[1];
    const float* s1 = (const float*)d_in[2];
    const float* a0 = (const float*)d_in[3];
    const float* a1 = (const float*)d_in[4];

    k_T<<<dim3(JTILES, ITILES, NB * PC), NTHR_T>>>(x, s0, s1, a0, a1);
    k_energy<<<dim3(NP / PTS, NB, NC), 256>>>(x, (float*)d_out);
}